// round 3
// baseline (speedup 1.0000x reference)
#include <cuda_runtime.h>
#include <cooperative_groups.h>
#include <math.h>

namespace cg = cooperative_groups;

constexpr int BATCH = 32;
constexpr int TLEN  = 2048;
constexpr int DIM   = 256;
constexpr float THRESH = 0.3f;

// Precomputed x-part preactivations: P[t][b][g*256+d], g in {ff1, ff2, tgate}
__device__ float g_P[(size_t)TLEN * BATCH * 768];

// ---------------- packed f32x2 helpers (FFMA2 path ptxas won't emit) -------
__device__ __forceinline__ unsigned long long pk2(float lo, float hi) {
    unsigned long long r;
    asm("mov.b64 %0, {%1, %2};" : "=l"(r) : "f"(lo), "f"(hi));
    return r;
}
__device__ __forceinline__ void upk2(float& lo, float& hi, unsigned long long v) {
    asm("mov.b64 {%0, %1}, %2;" : "=f"(lo), "=f"(hi) : "l"(v));
}
#define FMA2(acc, a, b) asm("fma.rn.f32x2 %0, %1, %2, %0;" : "+l"(acc) : "l"(a), "l"(b))

// ---------------- mbarrier / DSMEM helpers ---------------------------------
__device__ __forceinline__ unsigned smem_u32(const void* p) {
    unsigned a;
    asm("{ .reg .u64 t; cvta.to.shared.u64 t, %1; cvt.u32.u64 %0, t; }" : "=r"(a) : "l"(p));
    return a;
}
__device__ __forceinline__ unsigned mapa_u32(unsigned addr, unsigned rank) {
    unsigned r;
    asm("mapa.shared::cluster.u32 %0, %1, %2;" : "=r"(r) : "r"(addr), "r"(rank));
    return r;
}
__device__ __forceinline__ void mbar_init(unsigned addr, unsigned count) {
    asm volatile("mbarrier.init.shared.b64 [%0], %1;" :: "r"(addr), "r"(count) : "memory");
}
__device__ __forceinline__ void mbar_arrive_cluster(unsigned caddr) {
    asm volatile("mbarrier.arrive.release.cluster.shared::cluster.b64 _, [%0];"
                 :: "r"(caddr) : "memory");
}
__device__ __forceinline__ void st_cluster_f32(unsigned caddr, float v) {
    asm volatile("st.shared::cluster.f32 [%0], %1;" :: "r"(caddr), "f"(v) : "memory");
}
__device__ __forceinline__ void fence_cluster() {
    asm volatile("fence.acq_rel.cluster;" ::: "memory");
}
__device__ __forceinline__ void mbar_wait_acq_cluster(unsigned addr, unsigned parity) {
    unsigned done;
    asm volatile(
        "{\n\t.reg .pred p;\n\t"
        "mbarrier.try_wait.parity.acquire.cluster.shared::cta.b64 p, [%1], %2;\n\t"
        "selp.b32 %0, 1, 0, p;\n\t}"
        : "=r"(done) : "r"(addr), "r"(parity) : "memory");
    if (!done) {
        asm volatile(
            "{\n\t.reg .pred P1;\n\t"
            "WL_%=:\n\t"
            "mbarrier.try_wait.parity.acquire.cluster.shared::cta.b64 P1, [%0], %1, 0x989680;\n\t"
            "@P1 bra.uni WD_%=;\n\t"
            "bra.uni WL_%=;\n\t"
            "WD_%=:\n\t}"
            :: "r"(addr), "r"(parity) : "memory");
    }
}

// ---------------------------------------------------------------------------
// Phase 1: P = x @ Wx + bias (x-part only, gates {W1, W2, Wta+Wtb}).
// 128x128x16 tile, 256 threads, 8x8 microtile, FFMA2 inner product.
// ---------------------------------------------------------------------------
__global__ __launch_bounds__(256) void px_gemm(
    const float* __restrict__ x,
    const float* __restrict__ W1,  const float* __restrict__ b1,
    const float* __restrict__ W2,  const float* __restrict__ b2,
    const float* __restrict__ Wta, const float* __restrict__ bta,
    const float* __restrict__ Wtb, const float* __restrict__ btb)
{
    __shared__ __align__(16) float As[16][132];
    __shared__ __align__(16) float Bs[16][128];

    const int nt    = blockIdx.x;          // 0..5
    const int mt    = blockIdx.y;          // 0..511
    const int gate  = nt >> 1;
    const int ncol0 = (nt & 1) * 128;
    const float* __restrict__ Wg = (gate == 0) ? W1 : (gate == 1) ? W2 : Wta;

    const int tid = threadIdx.x;
    const int tn  = (tid & 15) * 8;
    const int tm  = (tid >> 4) * 8;
    const int m0  = mt * 128;

    unsigned long long acc2[8][4];
    #pragma unroll
    for (int i = 0; i < 8; i++)
        #pragma unroll
        for (int j = 0; j < 4; j++) acc2[i][j] = 0ull;

    for (int k0 = 0; k0 < 256; k0 += 16) {
        #pragma unroll
        for (int i = 0; i < 2; i++) {
            int idx = tid + i * 256;
            int ml  = idx >> 2;
            int k4  = (idx & 3) * 4;
            int m   = m0 + ml;
            int b   = m & 31;
            int t   = m >> 5;
            float4 v = *(const float4*)&x[((size_t)b * TLEN + t) * 256 + k0 + k4];
            As[k4 + 0][ml] = v.x;
            As[k4 + 1][ml] = v.y;
            As[k4 + 2][ml] = v.z;
            As[k4 + 3][ml] = v.w;
        }
        #pragma unroll
        for (int i = 0; i < 2; i++) {
            int idx = tid + i * 256;
            int kl  = idx >> 5;
            int nl4 = (idx & 31) * 4;
            size_t off = (size_t)(k0 + kl) * 256 + ncol0 + nl4;
            float4 v = *(const float4*)&Wg[off];
            if (gate == 2) {
                float4 v2 = *(const float4*)&Wtb[off];
                v.x += v2.x; v.y += v2.y; v.z += v2.z; v.w += v2.w;
            }
            *(float4*)&Bs[kl][nl4] = v;
        }
        __syncthreads();
        #pragma unroll
        for (int k = 0; k < 16; k++) {
            float4 a0 = *(const float4*)&As[k][tm];
            float4 a1 = *(const float4*)&As[k][tm + 4];
            float av[8] = {a0.x, a0.y, a0.z, a0.w, a1.x, a1.y, a1.z, a1.w};
            unsigned long long ap[8];
            #pragma unroll
            for (int i = 0; i < 8; i++) ap[i] = pk2(av[i], av[i]);
            const unsigned long long* bp = (const unsigned long long*)&Bs[k][tn];
            unsigned long long bq0 = bp[0], bq1 = bp[1], bq2 = bp[2], bq3 = bp[3];
            #pragma unroll
            for (int ii = 0; ii < 8; ii++) {
                FMA2(acc2[ii][0], ap[ii], bq0);
                FMA2(acc2[ii][1], ap[ii], bq1);
                FMA2(acc2[ii][2], ap[ii], bq2);
                FMA2(acc2[ii][3], ap[ii], bq3);
            }
        }
        __syncthreads();
    }

    const float* __restrict__ biasA = (gate == 0) ? b1 : (gate == 1) ? b2 : bta;
    float bias[8];
    #pragma unroll
    for (int jj = 0; jj < 8; jj++) {
        float bb = biasA[ncol0 + tn + jj];
        if (gate == 2) bb += btb[ncol0 + tn + jj];
        bias[jj] = bb;
    }
    #pragma unroll
    for (int ii = 0; ii < 8; ii++) {
        float c[8];
        #pragma unroll
        for (int jp = 0; jp < 4; jp++) upk2(c[2*jp], c[2*jp+1], acc2[ii][jp]);
        size_t rowo = (size_t)(m0 + tm + ii) * 768 + (size_t)nt * 128 + tn;
        float4 o0, o1;
        o0.x = c[0] + bias[0]; o0.y = c[1] + bias[1];
        o0.z = c[2] + bias[2]; o0.w = c[3] + bias[3];
        o1.x = c[4] + bias[4]; o1.y = c[5] + bias[5];
        o1.z = c[6] + bias[6]; o1.w = c[7] + bias[7];
        *(float4*)&g_P[rowo]     = o0;
        *(float4*)&g_P[rowo + 4] = o1;
    }
}

// ---------------------------------------------------------------------------
// Phase 2: CfC scan + fused PLIF. 16 clusters x 8 CTAs; weights in registers
// (paired f32x2), depth-4 h ring, mbarrier producer/consumer sync.
// Tail-safe: no remote op may target a CTA that could have exited; final
// cluster.sync() bounds exit skew.
// ---------------------------------------------------------------------------
constexpr int HBUF = 4;

__global__ void __launch_bounds__(384, 1) __cluster_dims__(8, 1, 1)
cfc_scan(const float* __restrict__ W1,
         const float* __restrict__ W2,
         const float* __restrict__ Wta,
         const float* __restrict__ Wtb,
         const float* __restrict__ plif_w,
         float* __restrict__ out)
{
    __shared__ __align__(16) float h_sh[HBUF][2][DIM];     // ring of h states
    __shared__ __align__(16) float psum[4][2][96];
    __shared__ __align__(8)  unsigned long long mbar[2 * HBUF]; // [0..3]=full, [4..7]=free

    const unsigned rank = cg::this_cluster().block_rank();
    const int clu = blockIdx.x >> 3;
    const int b0  = clu * 2;

    const int tid = threadIdx.x;
    const int q   = tid / 96;
    const int col = tid % 96;
    const int g   = col >> 5;
    const int j   = col & 31;
    const int d   = (int)rank * 32 + j;

    const unsigned mb      = smem_u32(mbar);       // local full[0] addr
    const unsigned mb_free = mb + HBUF * 8;
    const unsigned h_base  = smem_u32(h_sh);

    unsigned full_rem[8], h_rem[8];
    #pragma unroll
    for (int r = 0; r < 8; r++) {
        full_rem[r] = mapa_u32(mb, r);
        h_rem[r]    = mapa_u32(h_base, r);
    }

    // ---- recurrent weights, packed as f32x2 over adjacent k ----
    const float* __restrict__ Wg = (g == 0) ? W1 : (g == 1) ? W2 : Wta;
    unsigned long long wp[32];
    #pragma unroll
    for (int i = 0; i < 32; i++) {
        size_t off0 = (size_t)(256 + q * 64 + 2 * i) * 256 + d;
        float v0 = Wg[off0], v1 = Wg[off0 + 256];
        if (g == 2) { v0 += Wtb[off0]; v1 += Wtb[off0 + 256]; }
        wp[i] = pk2(v0, v1);
    }

    const bool is_nl = (tid < 64);
    const int  nj = tid & 31;
    const int  nb = tid >> 5;
    const int  nd = (int)rank * 32 + nj;
    float decay = 0.f, mem = 0.f;
    if (is_nl) decay = 1.f / (1.f + expf(-plif_w[nd]));

    // init: zero h ring, init barriers
    for (int i = tid; i < HBUF * 2 * DIM; i += 384) ((float*)h_sh)[i] = 0.f;
    if (tid == 0) {
        #pragma unroll
        for (int i = 0; i < HBUF; i++) {
            mbar_init(mb + i * 8, 16);       // full: 2 warps x 8 CTAs
            mbar_init(mb_free + i * 8, 8);   // free: 1 per CTA
        }
    }
    __syncthreads();
    cg::this_cluster().sync();
    // pre-arm all free barriers (first-round writes never wait on real reads)
    if (tid == 0) {
        #pragma unroll
        for (int r = 0; r < 8; r++)
            #pragma unroll
            for (int i = 0; i < HBUF; i++)
                mbar_arrive_cluster(full_rem[r] + (HBUF + i) * 8);
    }

    // prefetch P for t=0
    float px0 = 0.f, px1 = 0.f, px2 = 0.f;
    if (is_nl) {
        const float* pr = g_P + (size_t)(b0 + nb) * 768 + nd;
        px0 = pr[0]; px1 = pr[256]; px2 = pr[512];
    }

    const size_t outB = (size_t)BATCH * TLEN * DIM;

    for (int t = 0; t < TLEN; t++) {
        const int b = t & 3;
        if (t > 0) mbar_wait_acq_cluster(mb + b * 8, ((unsigned)(t - 1) >> 2) & 1);

        // prefetch next P
        float pn0 = 0.f, pn1 = 0.f, pn2 = 0.f;
        if (is_nl) {
            int tnx = (t + 1 < TLEN) ? (t + 1) : t;
            const float* pr = g_P + ((size_t)tnx * BATCH + (b0 + nb)) * 768 + nd;
            pn0 = pr[0]; pn1 = pr[256]; pn2 = pr[512];
        }

        // k-loop: 64-k slice, both batches, FFMA2
        unsigned long long a0a = 0ull, a0b = 0ull, a1a = 0ull, a1b = 0ull;
        const ulonglong2* h0v = (const ulonglong2*)&h_sh[b][0][q * 64];
        const ulonglong2* h1v = (const ulonglong2*)&h_sh[b][1][q * 64];
        #pragma unroll
        for (int i4 = 0; i4 < 16; i4++) {
            ulonglong2 ha = h0v[i4];
            ulonglong2 hb = h1v[i4];
            FMA2(a0a, wp[2 * i4],     ha.x);
            FMA2(a0b, wp[2 * i4 + 1], ha.y);
            FMA2(a1a, wp[2 * i4],     hb.x);
            FMA2(a1b, wp[2 * i4 + 1], hb.y);
        }
        float l0, h0, l1, h1, l2, h2, l3, h3;
        upk2(l0, h0, a0a); upk2(l1, h1, a0b);
        upk2(l2, h2, a1a); upk2(l3, h3, a1b);
        psum[q][0][col] = (l0 + h0) + (l1 + h1);
        psum[q][1][col] = (l2 + h2) + (l3 + h3);
        __syncthreads();

        // signal "this CTA done reading h buffer b" to all ranks.
        // Only needed while a future writer (step t+4) exists; the guard also
        // keeps remote arrivals away from CTAs that may exit soon.
        if (tid == 352 && t + 4 < TLEN) {
            fence_cluster();
            #pragma unroll
            for (int r = 0; r < 8; r++)
                mbar_arrive_cluster(full_rem[r] + (HBUF + b) * 8);
        }

        if (is_nl) {
            float s0 = (psum[0][nb][nj]      + psum[1][nb][nj])
                     + (psum[2][nb][nj]      + psum[3][nb][nj])      + px0;
            float s1 = (psum[0][nb][32 + nj] + psum[1][nb][32 + nj])
                     + (psum[2][nb][32 + nj] + psum[3][nb][32 + nj]) + px1;
            float s2 = (psum[0][nb][64 + nj] + psum[1][nb][64 + nj])
                     + (psum[2][nb][64 + nj] + psum[3][nb][64 + nj]) + px2;

            float ff1 = tanhf(s0);
            float ff2 = tanhf(s1);
            float ti  = 1.f / (1.f + expf(-s2));
            float hn  = ff1 * (1.f - ti) + ti * ff2;

            // PLIF; forward spk == hard (soft cancels exactly in fp32)
            mem = decay * mem + hn;
            float spk = (mem >= THRESH) ? 1.f : 0.f;
            mem = mem - spk * THRESH;

            size_t o = ((size_t)(b0 + nb) * TLEN + t) * DIM + nd;
            out[o]            = hn;
            out[outB + o]     = spk;
            out[2 * outB + o] = mem;

            const int u = t + 1;
            if (u < TLEN) {
                const int ub = u & 3;
                // depth-4 ring: wait for readers of step u-4 (or pre-arm)
                mbar_wait_acq_cluster(mb_free + ub * 8, ((unsigned)u >> 2) & 1);
                const unsigned off = (unsigned)(((ub * 2 + nb) * DIM + nd) * 4);
                #pragma unroll
                for (int r = 0; r < 8; r++)
                    st_cluster_f32(h_rem[r] + off, hn);
                __syncwarp();
                if ((tid & 31) == 0) {
                    fence_cluster();
                    #pragma unroll
                    for (int r = 0; r < 8; r++)
                        mbar_arrive_cluster(full_rem[r] + ub * 8);
                }
            }
        }
        px0 = pn0; px1 = pn1; px2 = pn2;
    }

    // No CTA may exit while peers might still send remote stores/arrivals here.
    cg::this_cluster().sync();
}

// ---------------------------------------------------------------------------
extern "C" void kernel_launch(void* const* d_in, const int* in_sizes, int n_in,
                              void* d_out, int out_size) {
    (void)in_sizes; (void)n_in; (void)out_size;
    const float* x   = (const float*)d_in[0];
    const float* W1  = (const float*)d_in[1];
    const float* b1  = (const float*)d_in[2];
    const float* W2  = (const float*)d_in[3];
    const float* b2  = (const float*)d_in[4];
    const float* Wta = (const float*)d_in[5];
    const float* bta = (const float*)d_in[6];
    const float* Wtb = (const float*)d_in[7];
    const float* btb = (const float*)d_in[8];
    const float* plw = (const float*)d_in[9];
    float* out = (float*)d_out;

    dim3 g1(6, 512);
    px_gemm<<<g1, 256>>>(x, W1, b1, W2, b2, Wta, bta, Wtb, btb);

    cfc_scan<<<128, 384>>>(W1, W2, Wta, Wtb, plw, out);
}

// round 4
// speedup vs baseline: 1.6772x; 1.6772x over previous
#include <cuda_runtime.h>
#include <cooperative_groups.h>
#include <math.h>

namespace cg = cooperative_groups;

constexpr int BATCH = 32;
constexpr int TLEN  = 2048;
constexpr int DIM   = 256;
constexpr float THRESH = 0.3f;

// Precomputed x-part preactivations: P[t][b][g*256+d], g in {ff1, ff2, tgate}
__device__ float g_P[(size_t)TLEN * BATCH * 768];

// ---------------- packed f32x2 helpers --------------------------------------
__device__ __forceinline__ unsigned long long pk2(float lo, float hi) {
    unsigned long long r;
    asm("mov.b64 %0, {%1, %2};" : "=l"(r) : "f"(lo), "f"(hi));
    return r;
}
__device__ __forceinline__ void upk2(float& lo, float& hi, unsigned long long v) {
    asm("mov.b64 {%0, %1}, %2;" : "=f"(lo), "=f"(hi) : "l"(v));
}
#define FMA2(acc, a, b) asm("fma.rn.f32x2 %0, %1, %2, %0;" : "+l"(acc) : "l"(a), "l"(b))

// ---------------- cluster helpers -------------------------------------------
__device__ __forceinline__ unsigned smem_u32(const void* p) {
    unsigned a;
    asm("{ .reg .u64 t; cvta.to.shared.u64 t, %1; cvt.u32.u64 %0, t; }" : "=r"(a) : "l"(p));
    return a;
}
__device__ __forceinline__ unsigned mapa_u32(unsigned addr, unsigned rank) {
    unsigned r;
    asm("mapa.shared::cluster.u32 %0, %1, %2;" : "=r"(r) : "r"(addr), "r"(rank));
    return r;
}
__device__ __forceinline__ void st_cluster_f32(unsigned caddr, float v) {
    asm volatile("st.shared::cluster.f32 [%0], %1;" :: "r"(caddr), "f"(v) : "memory");
}
__device__ __forceinline__ void cluster_arrive() {
    asm volatile("barrier.cluster.arrive.aligned;" ::: "memory");
}
__device__ __forceinline__ void cluster_wait() {
    asm volatile("barrier.cluster.wait.aligned;" ::: "memory");
}

// ---------------------------------------------------------------------------
// Phase 1: P = x @ Wx + bias (x-part only, gates {W1, W2, Wta+Wtb}).
// 128x128x16 tile, 256 threads, 8x8 microtile, FFMA2 (n-packed: k-order per
// output unchanged -> P bitwise identical to scalar version).
// ---------------------------------------------------------------------------
__global__ __launch_bounds__(256) void px_gemm(
    const float* __restrict__ x,
    const float* __restrict__ W1,  const float* __restrict__ b1,
    const float* __restrict__ W2,  const float* __restrict__ b2,
    const float* __restrict__ Wta, const float* __restrict__ bta,
    const float* __restrict__ Wtb, const float* __restrict__ btb)
{
    __shared__ __align__(16) float As[16][132];
    __shared__ __align__(16) float Bs[16][128];

    const int nt    = blockIdx.x;          // 0..5
    const int mt    = blockIdx.y;          // 0..511
    const int gate  = nt >> 1;
    const int ncol0 = (nt & 1) * 128;
    const float* __restrict__ Wg = (gate == 0) ? W1 : (gate == 1) ? W2 : Wta;

    const int tid = threadIdx.x;
    const int tn  = (tid & 15) * 8;
    const int tm  = (tid >> 4) * 8;
    const int m0  = mt * 128;

    unsigned long long acc2[8][4];
    #pragma unroll
    for (int i = 0; i < 8; i++)
        #pragma unroll
        for (int j = 0; j < 4; j++) acc2[i][j] = 0ull;

    for (int k0 = 0; k0 < 256; k0 += 16) {
        #pragma unroll
        for (int i = 0; i < 2; i++) {
            int idx = tid + i * 256;
            int ml  = idx >> 2;
            int k4  = (idx & 3) * 4;
            int m   = m0 + ml;
            int b   = m & 31;
            int t   = m >> 5;
            float4 v = *(const float4*)&x[((size_t)b * TLEN + t) * 256 + k0 + k4];
            As[k4 + 0][ml] = v.x;
            As[k4 + 1][ml] = v.y;
            As[k4 + 2][ml] = v.z;
            As[k4 + 3][ml] = v.w;
        }
        #pragma unroll
        for (int i = 0; i < 2; i++) {
            int idx = tid + i * 256;
            int kl  = idx >> 5;
            int nl4 = (idx & 31) * 4;
            size_t off = (size_t)(k0 + kl) * 256 + ncol0 + nl4;
            float4 v = *(const float4*)&Wg[off];
            if (gate == 2) {
                float4 v2 = *(const float4*)&Wtb[off];
                v.x += v2.x; v.y += v2.y; v.z += v2.z; v.w += v2.w;
            }
            *(float4*)&Bs[kl][nl4] = v;
        }
        __syncthreads();
        #pragma unroll
        for (int k = 0; k < 16; k++) {
            float4 a0 = *(const float4*)&As[k][tm];
            float4 a1 = *(const float4*)&As[k][tm + 4];
            float av[8] = {a0.x, a0.y, a0.z, a0.w, a1.x, a1.y, a1.z, a1.w};
            unsigned long long ap[8];
            #pragma unroll
            for (int i = 0; i < 8; i++) ap[i] = pk2(av[i], av[i]);
            const unsigned long long* bp = (const unsigned long long*)&Bs[k][tn];
            unsigned long long bq0 = bp[0], bq1 = bp[1], bq2 = bp[2], bq3 = bp[3];
            #pragma unroll
            for (int ii = 0; ii < 8; ii++) {
                FMA2(acc2[ii][0], ap[ii], bq0);
                FMA2(acc2[ii][1], ap[ii], bq1);
                FMA2(acc2[ii][2], ap[ii], bq2);
                FMA2(acc2[ii][3], ap[ii], bq3);
            }
        }
        __syncthreads();
    }

    const float* __restrict__ biasA = (gate == 0) ? b1 : (gate == 1) ? b2 : bta;
    float bias[8];
    #pragma unroll
    for (int jj = 0; jj < 8; jj++) {
        float bb = biasA[ncol0 + tn + jj];
        if (gate == 2) bb += btb[ncol0 + tn + jj];
        bias[jj] = bb;
    }
    #pragma unroll
    for (int ii = 0; ii < 8; ii++) {
        float c[8];
        #pragma unroll
        for (int jp = 0; jp < 4; jp++) upk2(c[2*jp], c[2*jp+1], acc2[ii][jp]);
        size_t rowo = (size_t)(m0 + tm + ii) * 768 + (size_t)nt * 128 + tn;
        float4 o0, o1;
        o0.x = c[0] + bias[0]; o0.y = c[1] + bias[1];
        o0.z = c[2] + bias[2]; o0.w = c[3] + bias[3];
        o1.x = c[4] + bias[4]; o1.y = c[5] + bias[5];
        o1.z = c[6] + bias[6]; o1.w = c[7] + bias[7];
        *(float4*)&g_P[rowo]     = o0;
        *(float4*)&g_P[rowo + 4] = o1;
    }
}

// ---------------------------------------------------------------------------
// Phase 2: CfC scan + fused PLIF. 16 clusters x 8 CTAs; recurrent weights in
// registers (f32x2 over adjacent k). The two batches of a cluster are
// software-pipelined against the split HW cluster barrier: each WAIT's phase
// was armed while computing the other batch.
//
// Per iteration t (phases alternate; arrive/wait strictly alternating):
//   kloopA(t); sync; nlA -> push hA(t+1); [t>0] WAIT(2t-1); ARRIVE(2t);
//   kloopB(t); sync; nlB -> push hB(t+1);        WAIT(2t);  [t<T-1] ARRIVE(2t+1)
// Phase 2t   completion => all pushed hA(t+1); consumed by kloopA(t+1).
// Phase 2t+1 completion => all pushed hB(t+1); consumed by kloopB(t+1).
// Overwrite safety: pushX(t+1) is preceded (same CTA) by a wait whose phase
// required every peer's arrive issued after its kloopX(t-1) reads.
// ---------------------------------------------------------------------------
__global__ void __launch_bounds__(384, 1) __cluster_dims__(8, 1, 1)
cfc_scan(const float* __restrict__ W1,
         const float* __restrict__ W2,
         const float* __restrict__ Wta,
         const float* __restrict__ Wtb,
         const float* __restrict__ plif_w,
         float* __restrict__ out)
{
    __shared__ __align__(16) float hA[2][DIM];   // batch b0,   double-buffered
    __shared__ __align__(16) float hB[2][DIM];   // batch b0+1
    __shared__ __align__(16) float psA[4][96];
    __shared__ __align__(16) float psB[4][96];

    const unsigned rank = cg::this_cluster().block_rank();
    const int b0  = (blockIdx.x >> 3) * 2;

    const int tid  = threadIdx.x;
    const int q    = tid / 96;
    const int col  = tid % 96;
    const int g    = col >> 5;
    const int j    = col & 31;
    const int d    = (int)rank * 32 + j;
    const int wid  = tid >> 5;
    const int lane = tid & 31;

    // ---- recurrent weights, f32x2 over adjacent k (64 regs) ----
    const float* __restrict__ Wg = (g == 0) ? W1 : (g == 1) ? W2 : Wta;
    unsigned long long wp[32];
    #pragma unroll
    for (int i = 0; i < 32; i++) {
        size_t off0 = (size_t)(256 + q * 64 + 2 * i) * 256 + d;
        float v0 = Wg[off0], v1 = Wg[off0 + 256];
        if (g == 2) { v0 += Wtb[off0]; v1 += Wtb[off0 + 256]; }
        wp[i] = pk2(v0, v1);
    }

    // nl roles: warp 0 -> batch b0 (buffer hA), warp 1 -> batch b0+1 (hB)
    const bool is_nl = (wid < 2);
    const int  nd = (int)rank * 32 + lane;
    float decay = 0.f, mem = 0.f;
    unsigned h_rem[8];
    if (is_nl) {
        decay = 1.f / (1.f + expf(-plif_w[nd]));
        unsigned hb = smem_u32(wid == 0 ? (const void*)hA : (const void*)hB);
        #pragma unroll
        for (int r = 0; r < 8; r++) h_rem[r] = mapa_u32(hb, r);
    }

    // init h=0, prologue rendezvous
    for (int i = tid; i < 2 * DIM; i += 384) { hA[0][i] = 0.f; hB[0][i] = 0.f; }
    __syncthreads();
    cg::this_cluster().sync();

    // prefetch P for t=0 (warp w handles batch b0+w)
    float px0 = 0.f, px1 = 0.f, px2 = 0.f;
    if (is_nl) {
        const float* pr = g_P + (size_t)(b0 + wid) * 768 + nd;
        px0 = pr[0]; px1 = pr[256]; px2 = pr[512];
    }

    const size_t outB = (size_t)BATCH * TLEN * DIM;

    for (int t = 0; t < TLEN; t++) {
        const int ph = t & 1;

        // prefetch next P (overlaps everything below)
        float pn0 = 0.f, pn1 = 0.f, pn2 = 0.f;
        if (is_nl) {
            int tnx = (t + 1 < TLEN) ? (t + 1) : t;
            const float* pr = g_P + ((size_t)tnx * BATCH + (b0 + wid)) * 768 + nd;
            pn0 = pr[0]; pn1 = pr[256]; pn2 = pr[512];
        }

        // ---- batch A ----
        {
            unsigned long long acc = 0ull;
            const ulonglong2* hv = (const ulonglong2*)&hA[ph][q * 64];
            #pragma unroll
            for (int i2 = 0; i2 < 16; i2++) {
                ulonglong2 hp = hv[i2];
                FMA2(acc, wp[2 * i2],     hp.x);
                FMA2(acc, wp[2 * i2 + 1], hp.y);
            }
            float lo, hi; upk2(lo, hi, acc);
            psA[q][col] = lo + hi;
        }
        __syncthreads();

        if (wid == 0) {
            float s0 = ((psA[0][lane]      + psA[1][lane])      + psA[2][lane])      + psA[3][lane]      + px0;
            float s1 = ((psA[0][32 + lane] + psA[1][32 + lane]) + psA[2][32 + lane]) + psA[3][32 + lane] + px1;
            float s2 = ((psA[0][64 + lane] + psA[1][64 + lane]) + psA[2][64 + lane]) + psA[3][64 + lane] + px2;
            float ff1 = tanhf(s0);
            float ff2 = tanhf(s1);
            float ti  = 1.f / (1.f + expf(-s2));
            float hn  = ff1 * (1.f - ti) + ti * ff2;

            if (t + 1 < TLEN) {                      // push h first
                const unsigned off = (unsigned)((((t + 1) & 1) * DIM + nd) * 4);
                #pragma unroll
                for (int r = 0; r < 8; r++) st_cluster_f32(h_rem[r] + off, hn);
            }
            mem = decay * mem + hn;                  // PLIF (spk == hard exactly)
            float spk = (mem >= THRESH) ? 1.f : 0.f;
            mem = mem - spk * THRESH;
            size_t o = ((size_t)b0 * TLEN + t) * DIM + nd;
            out[o] = hn; out[outB + o] = spk; out[2 * outB + o] = mem;
        }

        if (t > 0) cluster_wait();   // phase 2t-1: hB(t) visible (armed during iter t-1 tail)
        cluster_arrive();            // phase 2t: my hA(t+1) push released

        // ---- batch B ----
        {
            unsigned long long acc = 0ull;
            const ulonglong2* hv = (const ulonglong2*)&hB[ph][q * 64];
            #pragma unroll
            for (int i2 = 0; i2 < 16; i2++) {
                ulonglong2 hp = hv[i2];
                FMA2(acc, wp[2 * i2],     hp.x);
                FMA2(acc, wp[2 * i2 + 1], hp.y);
            }
            float lo, hi; upk2(lo, hi, acc);
            psB[q][col] = lo + hi;
        }
        __syncthreads();

        if (wid == 1) {
            float s0 = ((psB[0][lane]      + psB[1][lane])      + psB[2][lane])      + psB[3][lane]      + px0;
            float s1 = ((psB[0][32 + lane] + psB[1][32 + lane]) + psB[2][32 + lane]) + psB[3][32 + lane] + px1;
            float s2 = ((psB[0][64 + lane] + psB[1][64 + lane]) + psB[2][64 + lane]) + psB[3][64 + lane] + px2;
            float ff1 = tanhf(s0);
            float ff2 = tanhf(s1);
            float ti  = 1.f / (1.f + expf(-s2));
            float hn  = ff1 * (1.f - ti) + ti * ff2;

            if (t + 1 < TLEN) {
                const unsigned off = (unsigned)((((t + 1) & 1) * DIM + nd) * 4);
                #pragma unroll
                for (int r = 0; r < 8; r++) st_cluster_f32(h_rem[r] + off, hn);
            }
            mem = decay * mem + hn;
            float spk = (mem >= THRESH) ? 1.f : 0.f;
            mem = mem - spk * THRESH;
            size_t o = ((size_t)(b0 + 1) * TLEN + t) * DIM + nd;
            out[o] = hn; out[outB + o] = spk; out[2 * outB + o] = mem;
        }

        cluster_wait();                      // phase 2t: hA(t+1) visible (armed during batch B)
        if (t + 1 < TLEN) cluster_arrive();  // phase 2t+1: my hB(t+1) push released

        px0 = pn0; px1 = pn1; px2 = pn2;
    }

    // exit safety: no CTA leaves while peers' remote stores could be in flight
    cg::this_cluster().sync();
}

// ---------------------------------------------------------------------------
extern "C" void kernel_launch(void* const* d_in, const int* in_sizes, int n_in,
                              void* d_out, int out_size) {
    (void)in_sizes; (void)n_in; (void)out_size;
    const float* x   = (const float*)d_in[0];
    const float* W1  = (const float*)d_in[1];
    const float* b1  = (const float*)d_in[2];
    const float* W2  = (const float*)d_in[3];
    const float* b2  = (const float*)d_in[4];
    const float* Wta = (const float*)d_in[5];
    const float* bta = (const float*)d_in[6];
    const float* Wtb = (const float*)d_in[7];
    const float* btb = (const float*)d_in[8];
    const float* plw = (const float*)d_in[9];
    float* out = (float*)d_out;

    dim3 g1(6, 512);
    px_gemm<<<g1, 256>>>(x, W1, b1, W2, b2, Wta, bta, Wtb, btb);

    cfc_scan<<<128, 384>>>(W1, W2, Wta, Wtb, plw, out);
}

// round 5
// speedup vs baseline: 2.0845x; 1.2428x over previous
#include <cuda_runtime.h>
#include <cooperative_groups.h>
#include <math.h>

namespace cg = cooperative_groups;

constexpr int BATCH = 32;
constexpr int TLEN  = 2048;
constexpr int DIM   = 256;
constexpr float THRESH = 0.3f;

// Precomputed x-part preactivations: P[t][b][g*256+d], g in {ff1, ff2, tgate}
__device__ float g_P[(size_t)TLEN * BATCH * 768];

// ---------------- packed f32x2 helpers --------------------------------------
__device__ __forceinline__ unsigned long long pk2(float lo, float hi) {
    unsigned long long r;
    asm("mov.b64 %0, {%1, %2};" : "=l"(r) : "f"(lo), "f"(hi));
    return r;
}
__device__ __forceinline__ void upk2(float& lo, float& hi, unsigned long long v) {
    asm("mov.b64 {%0, %1}, %2;" : "=f"(lo), "=f"(hi) : "l"(v));
}
#define FMA2(acc, a, b) asm("fma.rn.f32x2 %0, %1, %2, %0;" : "+l"(acc) : "l"(a), "l"(b))

// ---------------- cluster / mbarrier helpers --------------------------------
__device__ __forceinline__ unsigned smem_u32(const void* p) {
    unsigned a;
    asm("{ .reg .u64 t; cvta.to.shared.u64 t, %1; cvt.u32.u64 %0, t; }" : "=r"(a) : "l"(p));
    return a;
}
__device__ __forceinline__ unsigned mapa_u32(unsigned addr, unsigned rank) {
    unsigned r;
    asm("mapa.shared::cluster.u32 %0, %1, %2;" : "=r"(r) : "r"(addr), "r"(rank));
    return r;
}
__device__ __forceinline__ void mbar_init(unsigned addr, unsigned count) {
    asm volatile("mbarrier.init.shared.b64 [%0], %1;" :: "r"(addr), "r"(count) : "memory");
}
__device__ __forceinline__ void mbar_arrive_expect_tx(unsigned addr, unsigned bytes) {
    asm volatile("mbarrier.arrive.expect_tx.shared.b64 _, [%0], %1;"
                 :: "r"(addr), "r"(bytes) : "memory");
}
// Remote store with transaction-count completion on the REMOTE CTA's mbarrier.
__device__ __forceinline__ void st_async_f32(unsigned rem_addr, float v, unsigned rem_bar) {
    asm volatile("st.async.shared::cluster.mbarrier::complete_tx::bytes.b32 [%0], %1, [%2];"
                 :: "r"(rem_addr), "r"(__float_as_uint(v)), "r"(rem_bar) : "memory");
}
__device__ __forceinline__ void mbar_wait_parity(unsigned addr, unsigned parity) {
    unsigned done;
    asm volatile(
        "{\n\t.reg .pred p;\n\t"
        "mbarrier.try_wait.parity.acquire.cluster.shared::cta.b64 p, [%1], %2;\n\t"
        "selp.b32 %0, 1, 0, p;\n\t}"
        : "=r"(done) : "r"(addr), "r"(parity) : "memory");
    if (!done) {
        asm volatile(
            "{\n\t.reg .pred P1;\n\t"
            "WL_%=:\n\t"
            "mbarrier.try_wait.parity.acquire.cluster.shared::cta.b64 P1, [%0], %1, 0x989680;\n\t"
            "@P1 bra.uni WD_%=;\n\t"
            "bra.uni WL_%=;\n\t"
            "WD_%=:\n\t}"
            :: "r"(addr), "r"(parity) : "memory");
    }
}

// ---------------------------------------------------------------------------
// Phase 1: P = x @ Wx + bias (x-part only, gates {W1, W2, Wta+Wtb}).
// 128x128x16 tile, 256 threads, 8x8 microtile, FFMA2 inner product.
// (unchanged from R4 — P bitwise identical)
// ---------------------------------------------------------------------------
__global__ __launch_bounds__(256) void px_gemm(
    const float* __restrict__ x,
    const float* __restrict__ W1,  const float* __restrict__ b1,
    const float* __restrict__ W2,  const float* __restrict__ b2,
    const float* __restrict__ Wta, const float* __restrict__ bta,
    const float* __restrict__ Wtb, const float* __restrict__ btb)
{
    __shared__ __align__(16) float As[16][132];
    __shared__ __align__(16) float Bs[16][128];

    const int nt    = blockIdx.x;          // 0..5
    const int mt    = blockIdx.y;          // 0..511
    const int gate  = nt >> 1;
    const int ncol0 = (nt & 1) * 128;
    const float* __restrict__ Wg = (gate == 0) ? W1 : (gate == 1) ? W2 : Wta;

    const int tid = threadIdx.x;
    const int tn  = (tid & 15) * 8;
    const int tm  = (tid >> 4) * 8;
    const int m0  = mt * 128;

    unsigned long long acc2[8][4];
    #pragma unroll
    for (int i = 0; i < 8; i++)
        #pragma unroll
        for (int j = 0; j < 4; j++) acc2[i][j] = 0ull;

    for (int k0 = 0; k0 < 256; k0 += 16) {
        #pragma unroll
        for (int i = 0; i < 2; i++) {
            int idx = tid + i * 256;
            int ml  = idx >> 2;
            int k4  = (idx & 3) * 4;
            int m   = m0 + ml;
            int b   = m & 31;
            int t   = m >> 5;
            float4 v = *(const float4*)&x[((size_t)b * TLEN + t) * 256 + k0 + k4];
            As[k4 + 0][ml] = v.x;
            As[k4 + 1][ml] = v.y;
            As[k4 + 2][ml] = v.z;
            As[k4 + 3][ml] = v.w;
        }
        #pragma unroll
        for (int i = 0; i < 2; i++) {
            int idx = tid + i * 256;
            int kl  = idx >> 5;
            int nl4 = (idx & 31) * 4;
            size_t off = (size_t)(k0 + kl) * 256 + ncol0 + nl4;
            float4 v = *(const float4*)&Wg[off];
            if (gate == 2) {
                float4 v2 = *(const float4*)&Wtb[off];
                v.x += v2.x; v.y += v2.y; v.z += v2.z; v.w += v2.w;
            }
            *(float4*)&Bs[kl][nl4] = v;
        }
        __syncthreads();
        #pragma unroll
        for (int k = 0; k < 16; k++) {
            float4 a0 = *(const float4*)&As[k][tm];
            float4 a1 = *(const float4*)&As[k][tm + 4];
            float av[8] = {a0.x, a0.y, a0.z, a0.w, a1.x, a1.y, a1.z, a1.w};
            unsigned long long ap[8];
            #pragma unroll
            for (int i = 0; i < 8; i++) ap[i] = pk2(av[i], av[i]);
            const unsigned long long* bp = (const unsigned long long*)&Bs[k][tn];
            unsigned long long bq0 = bp[0], bq1 = bp[1], bq2 = bp[2], bq3 = bp[3];
            #pragma unroll
            for (int ii = 0; ii < 8; ii++) {
                FMA2(acc2[ii][0], ap[ii], bq0);
                FMA2(acc2[ii][1], ap[ii], bq1);
                FMA2(acc2[ii][2], ap[ii], bq2);
                FMA2(acc2[ii][3], ap[ii], bq3);
            }
        }
        __syncthreads();
    }

    const float* __restrict__ biasA = (gate == 0) ? b1 : (gate == 1) ? b2 : bta;
    float bias[8];
    #pragma unroll
    for (int jj = 0; jj < 8; jj++) {
        float bb = biasA[ncol0 + tn + jj];
        if (gate == 2) bb += btb[ncol0 + tn + jj];
        bias[jj] = bb;
    }
    #pragma unroll
    for (int ii = 0; ii < 8; ii++) {
        float c[8];
        #pragma unroll
        for (int jp = 0; jp < 4; jp++) upk2(c[2*jp], c[2*jp+1], acc2[ii][jp]);
        size_t rowo = (size_t)(m0 + tm + ii) * 768 + (size_t)nt * 128 + tn;
        float4 o0, o1;
        o0.x = c[0] + bias[0]; o0.y = c[1] + bias[1];
        o0.z = c[2] + bias[2]; o0.w = c[3] + bias[3];
        o1.x = c[4] + bias[4]; o1.y = c[5] + bias[5];
        o1.z = c[6] + bias[6]; o1.w = c[7] + bias[7];
        *(float4*)&g_P[rowo]     = o0;
        *(float4*)&g_P[rowo + 4] = o1;
    }
}

// ---------------------------------------------------------------------------
// Phase 2: CfC scan + fused PLIF. 16 clusters x 8 CTAs; recurrent weights in
// registers (f32x2 over adjacent k). h exchange via st.async (remote store +
// tx-count completion on the destination's LOCAL mbarrier). No cluster.sync,
// no cluster fences in the loop.
//
// Double-buffered h; bar[b] guards buffer b. Per use, bar expects 2048 B
// (2 batches x 256 dims x 4 B) + 1 local arrive (the re-arm).
// Safety chain: my bar(t) fired => every peer pushed h(t) => every peer
// passed its __syncthreads after kloop(t-1) => buffer (t+1)&1 is free to
// overwrite cluster-wide. Arm(t+2) happens before my h(t+1) push (arm ->
// __syncthreads -> push), so next-phase tx causally follow the arm.
// ---------------------------------------------------------------------------
__global__ void __launch_bounds__(384, 1) __cluster_dims__(8, 1, 1)
cfc_scan(const float* __restrict__ W1,
         const float* __restrict__ W2,
         const float* __restrict__ Wta,
         const float* __restrict__ Wtb,
         const float* __restrict__ plif_w,
         float* __restrict__ out)
{
    __shared__ __align__(16) float h_sh[2][2][DIM];     // [buf][batch][dim]
    __shared__ __align__(16) float ps[4][2][96];        // [kq][batch][col]
    __shared__ __align__(8)  unsigned long long mbar[2];

    const unsigned rank = cg::this_cluster().block_rank();
    const int b0  = (blockIdx.x >> 3) * 2;

    const int tid  = threadIdx.x;
    const int q    = tid / 96;
    const int col  = tid % 96;
    const int g    = col >> 5;
    const int j    = col & 31;
    const int d    = (int)rank * 32 + j;
    const int wid  = tid >> 5;
    const int lane = tid & 31;

    const unsigned mb     = smem_u32(mbar);
    const unsigned h_base = smem_u32(h_sh);

    // ---- recurrent weights, f32x2 over adjacent k (64 regs) ----
    const float* __restrict__ Wg = (g == 0) ? W1 : (g == 1) ? W2 : Wta;
    unsigned long long wp[32];
    #pragma unroll
    for (int i = 0; i < 32; i++) {
        size_t off0 = (size_t)(256 + q * 64 + 2 * i) * 256 + d;
        float v0 = Wg[off0], v1 = Wg[off0 + 256];
        if (g == 2) { v0 += Wtb[off0]; v1 += Wtb[off0 + 256]; }
        wp[i] = pk2(v0, v1);
    }

    // nl roles: warp 0 -> batch b0, warp 1 -> batch b0+1
    const bool is_nl = (wid < 2);
    const int  nb = wid;                 // batch index for nl warps
    const int  nd = (int)rank * 32 + lane;
    float decay = 0.f, mem = 0.f;
    unsigned h_rem[8], bar_rem[8];
    if (is_nl) {
        decay = 1.f / (1.f + expf(-plif_w[nd]));
        #pragma unroll
        for (int r = 0; r < 8; r++) {
            h_rem[r]   = mapa_u32(h_base, r);
            bar_rem[r] = mapa_u32(mb, r);
        }
    }

    // init: zero both h buffers, init + initial arms
    for (int i = tid; i < 2 * 2 * DIM; i += 384) ((float*)h_sh)[i] = 0.f;
    if (tid == 0) {
        mbar_init(mb, 1);         // bar[0] (first use t=2; armed in-loop at t=0)
        mbar_init(mb + 8, 1);     // bar[1] (first use t=1; armed here)
        mbar_arrive_expect_tx(mb + 8, 2048);
    }
    __syncthreads();
    cg::this_cluster().sync();    // mbarriers + zeroed h visible cluster-wide

    // prefetch P for t=0 (warp w handles batch b0+w)
    float px0 = 0.f, px1 = 0.f, px2 = 0.f;
    if (is_nl) {
        const float* pr = g_P + (size_t)(b0 + nb) * 768 + nd;
        px0 = pr[0]; px1 = pr[256]; px2 = pr[512];
    }

    const size_t outB = (size_t)BATCH * TLEN * DIM;
    unsigned p0 = 0, p1 = 0;      // per-buffer wait parities

    for (int t = 0; t < TLEN; t++) {
        const int b = t & 1;

        if (t > 0) {
            unsigned par = b ? p1 : p0;
            mbar_wait_parity(mb + (unsigned)b * 8, par);
            if (b) p1 ^= 1; else p0 ^= 1;
        }
        // re-arm bar[b] for its next use at t+2 (before this CTA pushes h(t+1))
        if (tid == 352) mbar_arrive_expect_tx(mb + (unsigned)b * 8, 2048);

        // prefetch next P
        float pn0 = 0.f, pn1 = 0.f, pn2 = 0.f;
        if (is_nl) {
            int tnx = (t + 1 < TLEN) ? (t + 1) : t;
            const float* pr = g_P + ((size_t)tnx * BATCH + (b0 + nb)) * 768 + nd;
            pn0 = pr[0]; pn1 = pr[256]; pn2 = pr[512];
        }

        // k-loop, both batches (accumulation order identical to R4)
        {
            unsigned long long accA = 0ull, accB = 0ull;
            const ulonglong2* hva = (const ulonglong2*)&h_sh[b][0][q * 64];
            const ulonglong2* hvb = (const ulonglong2*)&h_sh[b][1][q * 64];
            #pragma unroll
            for (int i2 = 0; i2 < 16; i2++) {
                ulonglong2 ha = hva[i2];
                ulonglong2 hb = hvb[i2];
                FMA2(accA, wp[2 * i2],     ha.x);
                FMA2(accA, wp[2 * i2 + 1], ha.y);
                FMA2(accB, wp[2 * i2],     hb.x);
                FMA2(accB, wp[2 * i2 + 1], hb.y);
            }
            float loA, hiA, loB, hiB;
            upk2(loA, hiA, accA);
            upk2(loB, hiB, accB);
            ps[q][0][col] = loA + hiA;
            ps[q][1][col] = loB + hiB;
        }
        __syncthreads();

        if (is_nl) {
            float s0 = ((ps[0][nb][lane]      + ps[1][nb][lane])      + ps[2][nb][lane])      + ps[3][nb][lane]      + px0;
            float s1 = ((ps[0][nb][32 + lane] + ps[1][nb][32 + lane]) + ps[2][nb][32 + lane]) + ps[3][nb][32 + lane] + px1;
            float s2 = ((ps[0][nb][64 + lane] + ps[1][nb][64 + lane]) + ps[2][nb][64 + lane]) + ps[3][nb][64 + lane] + px2;
            float ff1 = tanhf(s0);
            float ff2 = tanhf(s1);
            float ti  = 1.f / (1.f + expf(-s2));
            float hn  = ff1 * (1.f - ti) + ti * ff2;

            // push h(t+1) to all 8 ranks' buffer (t+1)&1, tx on their bar
            if (t + 1 < TLEN) {
                const int ub = (t + 1) & 1;
                const unsigned hoff = (unsigned)(((ub * 2 + nb) * DIM + nd) * 4);
                const unsigned boff = (unsigned)ub * 8;
                #pragma unroll
                for (int r = 0; r < 8; r++)
                    st_async_f32(h_rem[r] + hoff, hn, bar_rem[r] + boff);
            }

            // PLIF (forward spk == hard exactly in fp32)
            mem = decay * mem + hn;
            float spk = (mem >= THRESH) ? 1.f : 0.f;
            mem = mem - spk * THRESH;

            size_t o = ((size_t)(b0 + nb) * TLEN + t) * DIM + nd;
            out[o] = hn; out[outB + o] = spk; out[2 * outB + o] = mem;
        }

        px0 = pn0; px1 = pn1; px2 = pn2;
    }

    // all incoming st.async landed before our last wait; sync once for safety
    cg::this_cluster().sync();
}

// ---------------------------------------------------------------------------
extern "C" void kernel_launch(void* const* d_in, const int* in_sizes, int n_in,
                              void* d_out, int out_size) {
    (void)in_sizes; (void)n_in; (void)out_size;
    const float* x   = (const float*)d_in[0];
    const float* W1  = (const float*)d_in[1];
    const float* b1  = (const float*)d_in[2];
    const float* W2  = (const float*)d_in[3];
    const float* b2  = (const float*)d_in[4];
    const float* Wta = (const float*)d_in[5];
    const float* bta = (const float*)d_in[6];
    const float* Wtb = (const float*)d_in[7];
    const float* btb = (const float*)d_in[8];
    const float* plw = (const float*)d_in[9];
    float* out = (float*)d_out;

    dim3 g1(6, 512);
    px_gemm<<<g1, 256>>>(x, W1, b1, W2, b2, Wta, bta, Wtb, btb);

    cfc_scan<<<128, 384>>>(W1, W2, Wta, Wtb, plw, out);
}